// round 1
// baseline (speedup 1.0000x reference)
#include <cuda_runtime.h>
#include <math.h>

// Problem constants (fixed by the reference)
constexpr int NODES  = 100000;
constexpr int EDGES  = 1600000;
constexpr int GRAPHS = 64;
constexpr int DH     = 128;   // DI == DH == 128
constexpr int DOUT   = 10;

// Scratch (device globals: allocation-free rule)
__device__ float4 g_m  [NODES * 32];   // messages m[i] = (h@W) * dinv[i]
__device__ float4 g_agg[NODES * 32];   // aggregate accumulator
__device__ int    g_deg [NODES];
__device__ float  g_dinv[NODES];
__device__ float  g_hg  [GRAPHS * DH];

// ---------------------------------------------------------------------------
// Degree / normalization
// ---------------------------------------------------------------------------
__global__ void k_zero_deg() {
    int i = blockIdx.x * blockDim.x + threadIdx.x;
    if (i < NODES) g_deg[i] = 0;
}

__global__ void k_count_deg(const int* __restrict__ ei) {
    int e = blockIdx.x * blockDim.x + threadIdx.x;
    if (e < EDGES) atomicAdd(&g_deg[ei[EDGES + e]], 1);
}

__global__ void k_dinv() {
    int i = blockIdx.x * blockDim.x + threadIdx.x;
    if (i < NODES) g_dinv[i] = rsqrtf((float)(g_deg[i] + 1));  // +1 self loop
}

// ---------------------------------------------------------------------------
// GEMM: out_row = (pre(in_row)) @ W, scaled by dinv[row]; writes g_m AND g_agg
// pre(in) = in                      (use_pre == 0, first layer reads x)
// pre(in) = relu(in*dinv[row] + b)  (use_pre == 1, reads g_agg of prev layer)
// Block: 256 threads computes 64 rows x 128 cols; thread tile 8x4.
// ---------------------------------------------------------------------------
__global__ void __launch_bounds__(256) k_gemm(const float* __restrict__ xin,
                                              int use_pre,
                                              const float* __restrict__ W,
                                              const float* __restrict__ bias) {
    __shared__ float sh[64][DH];
    const float* in = use_pre ? (const float*)g_agg : xin;
    const int r0 = blockIdx.x * 64;

    // Load 64x128 input tile (fused relu/bias/dinv pre-transform)
    for (int i = threadIdx.x; i < 64 * 32; i += 256) {
        int r = i >> 5, kq = i & 31;
        int row = r0 + r;
        float4 v = make_float4(0.f, 0.f, 0.f, 0.f);
        if (row < NODES) {
            v = ((const float4*)in)[row * 32 + kq];
            if (use_pre) {
                float di = g_dinv[row];
                v.x = fmaxf(fmaf(v.x, di, bias[kq * 4 + 0]), 0.f);
                v.y = fmaxf(fmaf(v.y, di, bias[kq * 4 + 1]), 0.f);
                v.z = fmaxf(fmaf(v.z, di, bias[kq * 4 + 2]), 0.f);
                v.w = fmaxf(fmaf(v.w, di, bias[kq * 4 + 3]), 0.f);
            }
        }
        *(float4*)&sh[r][kq * 4] = v;
    }
    __syncthreads();

    const int cg = threadIdx.x & 31;  // col group: cols [cg*4, cg*4+4)
    const int rg = threadIdx.x >> 5;  // row group: rows [rg*8, rg*8+8)

    float acc[8][4];
#pragma unroll
    for (int r = 0; r < 8; r++)
#pragma unroll
        for (int c = 0; c < 4; c++) acc[r][c] = 0.f;

    const float4* W4 = (const float4*)W;
#pragma unroll 4
    for (int k = 0; k < DH; k++) {
        float4 w = W4[k * 32 + cg];       // coalesced, L1-resident
        float a[8];
#pragma unroll
        for (int r = 0; r < 8; r++) a[r] = sh[rg * 8 + r][k];  // smem broadcast
#pragma unroll
        for (int r = 0; r < 8; r++) {
            acc[r][0] = fmaf(a[r], w.x, acc[r][0]);
            acc[r][1] = fmaf(a[r], w.y, acc[r][1]);
            acc[r][2] = fmaf(a[r], w.z, acc[r][2]);
            acc[r][3] = fmaf(a[r], w.w, acc[r][3]);
        }
    }

    // Epilogue: scale by dinv[row]; write messages AND initialize accumulator.
    // agg init == m gives the self-loop term m[i]*dinv^2 after the consumer's
    // final *dinv[row].
#pragma unroll
    for (int r = 0; r < 8; r++) {
        int row = r0 + rg * 8 + r;
        if (row < NODES) {
            float di = g_dinv[row];
            float4 o = make_float4(acc[r][0] * di, acc[r][1] * di,
                                   acc[r][2] * di, acc[r][3] * di);
            g_m  [row * 32 + cg] = o;
            g_agg[row * 32 + cg] = o;
        }
    }
}

// ---------------------------------------------------------------------------
// Edge scatter: agg[dst] += m[src]   (pure vector reduction, warp per edge)
// ---------------------------------------------------------------------------
__global__ void __launch_bounds__(256) k_scatter(const int* __restrict__ ei) {
    int e = (blockIdx.x * 256 + threadIdx.x) >> 5;
    if (e >= EDGES) return;
    int lane = threadIdx.x & 31;
    int src = __ldg(&ei[e]);
    int dst = __ldg(&ei[EDGES + e]);
    float4 v = g_m[src * 32 + lane];          // random 512B gather (L2 resident)
    float4* p = &g_agg[dst * 32 + lane];
    asm volatile("red.global.add.v4.f32 [%0], {%1, %2, %3, %4};"
                 :: "l"(p), "f"(v.x), "f"(v.y), "f"(v.z), "f"(v.w)
                 : "memory");
}

// ---------------------------------------------------------------------------
// Global mean pool (batch is sorted): block per graph, binary-search range.
// Final conv output for node n, feat t = agg[n][t]*dinv[n] + b3[t].
// ---------------------------------------------------------------------------
__global__ void __launch_bounds__(128) k_pool(const int* __restrict__ batch,
                                              const float* __restrict__ b3) {
    int g = blockIdx.x, t = threadIdx.x;
    int lo = 0, hi = NODES;
    while (lo < hi) { int m = (lo + hi) >> 1; if (batch[m] < g) lo = m + 1; else hi = m; }
    int s = lo;
    hi = NODES;
    while (lo < hi) { int m = (lo + hi) >> 1; if (batch[m] <= g) lo = m + 1; else hi = m; }
    int e = lo;

    const float* agg = (const float*)g_agg;
    float sum = 0.f;
    for (int n = s; n < e; n++) sum = fmaf(agg[n * 128 + t], g_dinv[n], sum);
    int cnt = e - s;
    g_hg[g * DH + t] = (cnt > 0) ? (sum / (float)cnt + b3[t]) : 0.f;
}

// ---------------------------------------------------------------------------
// Head: softmax(hg @ Wl + bl) — one warp per graph.
// ---------------------------------------------------------------------------
__global__ void __launch_bounds__(32) k_head(const float* __restrict__ Wl,
                                             const float* __restrict__ bl,
                                             float* __restrict__ out) {
    int g = blockIdx.x, lane = threadIdx.x;
    float acc[DOUT];
#pragma unroll
    for (int c = 0; c < DOUT; c++) acc[c] = 0.f;

    for (int k = lane; k < DH; k += 32) {
        float h = g_hg[g * DH + k];
#pragma unroll
        for (int c = 0; c < DOUT; c++) acc[c] = fmaf(h, Wl[k * DOUT + c], acc[c]);
    }
#pragma unroll
    for (int off = 16; off > 0; off >>= 1)
#pragma unroll
        for (int c = 0; c < DOUT; c++)
            acc[c] += __shfl_xor_sync(0xFFFFFFFFu, acc[c], off);

    // every lane now has all 10 logits
    float mx = -1e30f;
#pragma unroll
    for (int c = 0; c < DOUT; c++) { acc[c] += bl[c]; mx = fmaxf(mx, acc[c]); }
    float sum = 0.f;
#pragma unroll
    for (int c = 0; c < DOUT; c++) { acc[c] = expf(acc[c] - mx); sum += acc[c]; }
    if (lane < DOUT) out[g * DOUT + lane] = acc[lane] / sum;
}

// ---------------------------------------------------------------------------
extern "C" void kernel_launch(void* const* d_in, const int* in_sizes, int n_in,
                              void* d_out, int out_size) {
    const float* x     = (const float*)d_in[0];
    const int*   ei    = (const int*)  d_in[1];
    const int*   batch = (const int*)  d_in[2];
    const float* W1 = (const float*)d_in[3];
    const float* b1 = (const float*)d_in[4];
    const float* W2 = (const float*)d_in[5];
    const float* b2 = (const float*)d_in[6];
    const float* W3 = (const float*)d_in[7];
    const float* b3 = (const float*)d_in[8];
    const float* Wl = (const float*)d_in[9];
    const float* bl = (const float*)d_in[10];
    float* out = (float*)d_out;

    const int gemm_grid    = (NODES + 63) / 64;
    const int scatter_grid = (EDGES * 32 + 255) / 256;

    k_zero_deg <<<(NODES + 255) / 256, 256>>>();
    k_count_deg<<<(EDGES + 255) / 256, 256>>>(ei);
    k_dinv     <<<(NODES + 255) / 256, 256>>>();

    // Layer 1
    k_gemm   <<<gemm_grid, 256>>>(x, 0, W1, nullptr);
    k_scatter<<<scatter_grid, 256>>>(ei);
    // Layer 2 (reads g_agg with fused relu/bias/dinv)
    k_gemm   <<<gemm_grid, 256>>>(nullptr, 1, W2, b1);
    k_scatter<<<scatter_grid, 256>>>(ei);
    // Layer 3
    k_gemm   <<<gemm_grid, 256>>>(nullptr, 1, W3, b2);
    k_scatter<<<scatter_grid, 256>>>(ei);

    k_pool<<<GRAPHS, 128>>>(batch, b3);
    k_head<<<GRAPHS, 32>>>(Wl, bl, out);
}

// round 2
// speedup vs baseline: 1.7184x; 1.7184x over previous
#include <cuda_runtime.h>
#include <cuda_fp16.h>
#include <math.h>

// Problem constants (fixed by the reference)
constexpr int NODES  = 100000;
constexpr int EDGES  = 1600000;
constexpr int GRAPHS = 64;
constexpr int DH     = 128;   // DI == DH == 128
constexpr int DOUT   = 10;

constexpr int NB = (NODES + 255) / 256;   // scan blocks (391)

// Scratch (device globals: allocation-free rule)
__device__ __half  g_mh [NODES * 128];    // messages m[i] = (h@W)*dinv[i], fp16 (25.6MB)
__device__ float4  g_agg[NODES * 32];     // aggregate (51.2MB)
__device__ int     g_deg [NODES];
__device__ float   g_dinv[NODES];
__device__ int     g_rowptr[NODES];       // CSR row start (end = start + deg)
__device__ int     g_cursor[NODES];
__device__ int     g_csr[EDGES];          // src indices grouped by dst
__device__ int     g_bsum[512];
__device__ float   g_hg  [GRAPHS * DH];

// ---------------------------------------------------------------------------
// Degree / normalization
// ---------------------------------------------------------------------------
__global__ void k_zero_deg() {
    int i = blockIdx.x * blockDim.x + threadIdx.x;
    if (i < NODES) g_deg[i] = 0;
}

__global__ void k_count_deg(const int* __restrict__ ei) {
    int e = blockIdx.x * blockDim.x + threadIdx.x;
    if (e < EDGES) atomicAdd(&g_deg[ei[EDGES + e]], 1);
}

__global__ void k_dinv() {
    int i = blockIdx.x * blockDim.x + threadIdx.x;
    if (i < NODES) g_dinv[i] = rsqrtf((float)(g_deg[i] + 1));  // +1 self loop
}

// ---------------------------------------------------------------------------
// CSR build: 3-kernel exclusive scan of g_deg, then atomic-cursor fill.
// ---------------------------------------------------------------------------
__global__ void k_scan_blocksum() {          // grid NB, block 256
    __shared__ float dummy;  (void)dummy;
    int i = blockIdx.x * 256 + threadIdx.x;
    int v = (i < NODES) ? g_deg[i] : 0;
    // warp + smem reduce
    __shared__ int wsum[8];
#pragma unroll
    for (int off = 16; off > 0; off >>= 1) v += __shfl_xor_sync(~0u, v, off);
    if ((threadIdx.x & 31) == 0) wsum[threadIdx.x >> 5] = v;
    __syncthreads();
    if (threadIdx.x < 8) {
        int s = wsum[threadIdx.x];
#pragma unroll
        for (int off = 4; off > 0; off >>= 1) s += __shfl_xor_sync(0xFFu, s, off);
        if (threadIdx.x == 0) g_bsum[blockIdx.x] = s;
    }
}

__global__ void k_scan_top() {               // single block of 512
    __shared__ int sh[512];
    int t = threadIdx.x;
    int v = (t < NB) ? g_bsum[t] : 0;
    sh[t] = v;
    __syncthreads();
    // Hillis-Steele inclusive
    for (int off = 1; off < 512; off <<= 1) {
        int add = (t >= off) ? sh[t - off] : 0;
        __syncthreads();
        sh[t] += add;
        __syncthreads();
    }
    if (t < NB) g_bsum[t] = sh[t] - v;       // exclusive
}

__global__ void k_scan_apply() {             // grid NB, block 256
    __shared__ int sh[256];
    int i = blockIdx.x * 256 + threadIdx.x;
    int t = threadIdx.x;
    int v = (i < NODES) ? g_deg[i] : 0;
    sh[t] = v;
    __syncthreads();
    for (int off = 1; off < 256; off <<= 1) {
        int add = (t >= off) ? sh[t - off] : 0;
        __syncthreads();
        sh[t] += add;
        __syncthreads();
    }
    if (i < NODES) {
        int start = g_bsum[blockIdx.x] + sh[t] - v;   // exclusive prefix
        g_rowptr[i] = start;
        g_cursor[i] = start;
    }
}

__global__ void k_csr_fill(const int* __restrict__ ei) {
    int e = blockIdx.x * blockDim.x + threadIdx.x;
    if (e < EDGES) {
        int src = ei[e], dst = ei[EDGES + e];
        int pos = atomicAdd(&g_cursor[dst], 1);
        g_csr[pos] = src;
    }
}

// ---------------------------------------------------------------------------
// GEMM: m_row = (pre(in_row)) @ W * dinv[row], written as fp16 to g_mh.
// pre(in) = in                      (use_pre == 0, first layer reads x)
// pre(in) = relu(in*dinv[row] + b)  (use_pre == 1, reads g_agg of prev layer)
// Block: 256 threads computes 64 rows x 128 cols; thread tile 8x4.
// ---------------------------------------------------------------------------
__global__ void __launch_bounds__(256) k_gemm(const float* __restrict__ xin,
                                              int use_pre,
                                              const float* __restrict__ W,
                                              const float* __restrict__ bias) {
    __shared__ float sh[64][DH];
    const float* in = use_pre ? (const float*)g_agg : xin;
    const int r0 = blockIdx.x * 64;

    for (int i = threadIdx.x; i < 64 * 32; i += 256) {
        int r = i >> 5, kq = i & 31;
        int row = r0 + r;
        float4 v = make_float4(0.f, 0.f, 0.f, 0.f);
        if (row < NODES) {
            v = ((const float4*)in)[row * 32 + kq];
            if (use_pre) {
                float di = g_dinv[row];
                v.x = fmaxf(fmaf(v.x, di, bias[kq * 4 + 0]), 0.f);
                v.y = fmaxf(fmaf(v.y, di, bias[kq * 4 + 1]), 0.f);
                v.z = fmaxf(fmaf(v.z, di, bias[kq * 4 + 2]), 0.f);
                v.w = fmaxf(fmaf(v.w, di, bias[kq * 4 + 3]), 0.f);
            }
        }
        *(float4*)&sh[r][kq * 4] = v;
    }
    __syncthreads();

    const int cg = threadIdx.x & 31;  // col group: cols [cg*4, cg*4+4)
    const int rg = threadIdx.x >> 5;  // row group: rows [rg*8, rg*8+8)

    float acc[8][4];
#pragma unroll
    for (int r = 0; r < 8; r++)
#pragma unroll
        for (int c = 0; c < 4; c++) acc[r][c] = 0.f;

    const float4* W4 = (const float4*)W;
#pragma unroll 4
    for (int k = 0; k < DH; k++) {
        float4 w = W4[k * 32 + cg];
        float a[8];
#pragma unroll
        for (int r = 0; r < 8; r++) a[r] = sh[rg * 8 + r][k];
#pragma unroll
        for (int r = 0; r < 8; r++) {
            acc[r][0] = fmaf(a[r], w.x, acc[r][0]);
            acc[r][1] = fmaf(a[r], w.y, acc[r][1]);
            acc[r][2] = fmaf(a[r], w.z, acc[r][2]);
            acc[r][3] = fmaf(a[r], w.w, acc[r][3]);
        }
    }

    // Epilogue: scale by dinv[row], convert to fp16, store 8B per thread-row.
#pragma unroll
    for (int r = 0; r < 8; r++) {
        int row = r0 + rg * 8 + r;
        if (row < NODES) {
            float di = g_dinv[row];
            union { uint2 u; __half2 h[2]; } pk;
            pk.h[0] = __floats2half2_rn(acc[r][0] * di, acc[r][1] * di);
            pk.h[1] = __floats2half2_rn(acc[r][2] * di, acc[r][3] * di);
            *(uint2*)(g_mh + row * 128 + cg * 4) = pk.u;
        }
    }
}

// ---------------------------------------------------------------------------
// CSR aggregation: agg[n] = m[n] (self loop) + sum_{src in csr row n} m[src].
// One warp per node; lane owns 4 features (8B half gather per src).
// ---------------------------------------------------------------------------
__global__ void __launch_bounds__(256) k_aggregate() {
    int node = blockIdx.x * 8 + (threadIdx.x >> 5);
    if (node >= NODES) return;
    int lane = threadIdx.x & 31;

    const __half* mh = g_mh;
    const int* __restrict__ csr = g_csr;

    float a0, a1, a2, a3;
    {   // self loop
        uint2 u = *(const uint2*)(mh + node * 128 + lane * 4);
        union { uint2 u; __half2 h[2]; } pk; pk.u = u;
        float2 f0 = __half22float2(pk.h[0]);
        float2 f1 = __half22float2(pk.h[1]);
        a0 = f0.x; a1 = f0.y; a2 = f1.x; a3 = f1.y;
    }

    int i = g_rowptr[node];
    int e = i + g_deg[node];

    for (; i + 4 <= e; i += 4) {
        int s0 = __ldg(csr + i + 0);
        int s1 = __ldg(csr + i + 1);
        int s2 = __ldg(csr + i + 2);
        int s3 = __ldg(csr + i + 3);
        uint2 u0 = *(const uint2*)(mh + s0 * 128 + lane * 4);
        uint2 u1 = *(const uint2*)(mh + s1 * 128 + lane * 4);
        uint2 u2 = *(const uint2*)(mh + s2 * 128 + lane * 4);
        uint2 u3 = *(const uint2*)(mh + s3 * 128 + lane * 4);
        union { uint2 u; __half2 h[2]; } p0, p1, p2, p3;
        p0.u = u0; p1.u = u1; p2.u = u2; p3.u = u3;
        float2 f;
        f = __half22float2(p0.h[0]); a0 += f.x; a1 += f.y;
        f = __half22float2(p0.h[1]); a2 += f.x; a3 += f.y;
        f = __half22float2(p1.h[0]); a0 += f.x; a1 += f.y;
        f = __half22float2(p1.h[1]); a2 += f.x; a3 += f.y;
        f = __half22float2(p2.h[0]); a0 += f.x; a1 += f.y;
        f = __half22float2(p2.h[1]); a2 += f.x; a3 += f.y;
        f = __half22float2(p3.h[0]); a0 += f.x; a1 += f.y;
        f = __half22float2(p3.h[1]); a2 += f.x; a3 += f.y;
    }
    for (; i < e; i++) {
        int s0 = __ldg(csr + i);
        uint2 u0 = *(const uint2*)(mh + s0 * 128 + lane * 4);
        union { uint2 u; __half2 h[2]; } p0; p0.u = u0;
        float2 f;
        f = __half22float2(p0.h[0]); a0 += f.x; a1 += f.y;
        f = __half22float2(p0.h[1]); a2 += f.x; a3 += f.y;
    }

    g_agg[node * 32 + lane] = make_float4(a0, a1, a2, a3);
}

// ---------------------------------------------------------------------------
// Global mean pool (batch is sorted): block per graph, binary-search range.
// Final conv output for node n, feat t = agg[n][t]*dinv[n] + b3[t].
// ---------------------------------------------------------------------------
__global__ void __launch_bounds__(128) k_pool(const int* __restrict__ batch,
                                              const float* __restrict__ b3) {
    int g = blockIdx.x, t = threadIdx.x;
    int lo = 0, hi = NODES;
    while (lo < hi) { int m = (lo + hi) >> 1; if (batch[m] < g) lo = m + 1; else hi = m; }
    int s = lo;
    hi = NODES;
    while (lo < hi) { int m = (lo + hi) >> 1; if (batch[m] <= g) lo = m + 1; else hi = m; }
    int e = lo;

    const float* agg = (const float*)g_agg;
    float sum = 0.f;
    for (int n = s; n < e; n++) sum = fmaf(agg[n * 128 + t], g_dinv[n], sum);
    int cnt = e - s;
    g_hg[g * DH + t] = (cnt > 0) ? (sum / (float)cnt + b3[t]) : 0.f;
}

// ---------------------------------------------------------------------------
// Head: softmax(hg @ Wl + bl) — one warp per graph.
// ---------------------------------------------------------------------------
__global__ void __launch_bounds__(32) k_head(const float* __restrict__ Wl,
                                             const float* __restrict__ bl,
                                             float* __restrict__ out) {
    int g = blockIdx.x, lane = threadIdx.x;
    float acc[DOUT];
#pragma unroll
    for (int c = 0; c < DOUT; c++) acc[c] = 0.f;

    for (int k = lane; k < DH; k += 32) {
        float h = g_hg[g * DH + k];
#pragma unroll
        for (int c = 0; c < DOUT; c++) acc[c] = fmaf(h, Wl[k * DOUT + c], acc[c]);
    }
#pragma unroll
    for (int off = 16; off > 0; off >>= 1)
#pragma unroll
        for (int c = 0; c < DOUT; c++)
            acc[c] += __shfl_xor_sync(0xFFFFFFFFu, acc[c], off);

    float mx = -1e30f;
#pragma unroll
    for (int c = 0; c < DOUT; c++) { acc[c] += bl[c]; mx = fmaxf(mx, acc[c]); }
    float sum = 0.f;
#pragma unroll
    for (int c = 0; c < DOUT; c++) { acc[c] = expf(acc[c] - mx); sum += acc[c]; }
    if (lane < DOUT) out[g * DOUT + lane] = acc[lane] / sum;
}

// ---------------------------------------------------------------------------
extern "C" void kernel_launch(void* const* d_in, const int* in_sizes, int n_in,
                              void* d_out, int out_size) {
    const float* x     = (const float*)d_in[0];
    const int*   ei    = (const int*)  d_in[1];
    const int*   batch = (const int*)  d_in[2];
    const float* W1 = (const float*)d_in[3];
    const float* b1 = (const float*)d_in[4];
    const float* W2 = (const float*)d_in[5];
    const float* b2 = (const float*)d_in[6];
    const float* W3 = (const float*)d_in[7];
    const float* b3 = (const float*)d_in[8];
    const float* Wl = (const float*)d_in[9];
    const float* bl = (const float*)d_in[10];
    float* out = (float*)d_out;

    const int gemm_grid = (NODES + 63) / 64;
    const int agg_grid  = (NODES + 7) / 8;

    // degrees + norm
    k_zero_deg <<<(NODES + 255) / 256, 256>>>();
    k_count_deg<<<(EDGES + 255) / 256, 256>>>(ei);
    k_dinv     <<<(NODES + 255) / 256, 256>>>();

    // CSR build (by dst)
    k_scan_blocksum<<<NB, 256>>>();
    k_scan_top     <<<1, 512>>>();
    k_scan_apply   <<<NB, 256>>>();
    k_csr_fill     <<<(EDGES + 255) / 256, 256>>>(ei);

    // Layer 1
    k_gemm     <<<gemm_grid, 256>>>(x, 0, W1, nullptr);
    k_aggregate<<<agg_grid, 256>>>();
    // Layer 2
    k_gemm     <<<gemm_grid, 256>>>(nullptr, 1, W2, b1);
    k_aggregate<<<agg_grid, 256>>>();
    // Layer 3
    k_gemm     <<<gemm_grid, 256>>>(nullptr, 1, W3, b2);
    k_aggregate<<<agg_grid, 256>>>();

    k_pool<<<GRAPHS, 128>>>(batch, b3);
    k_head<<<GRAPHS, 32>>>(Wl, bl, out);
}

// round 4
// speedup vs baseline: 2.5610x; 1.4903x over previous
#include <cuda_runtime.h>
#include <cuda_fp16.h>
#include <cstdint>
#include <stdint.h>
#include <math.h>

// Problem constants (fixed by the reference)
constexpr int NODES  = 100000;
constexpr int EDGES  = 1600000;
constexpr int GRAPHS = 64;
constexpr int DH     = 128;   // DI == DH == 128
constexpr int DOUT   = 10;

constexpr int NB = (NODES + 255) / 256;   // scan blocks (391)

// Scratch (device globals: allocation-free rule)
__device__ __half  g_mh [NODES * 128];    // messages m[i] = (h@W)*dinv[i], fp16
__device__ float4  g_agg[NODES * 32];     // aggregate (fp32)
__device__ int     g_deg [NODES];
__device__ float   g_dinv[NODES];
__device__ int     g_rowptr[NODES];       // CSR row start (end = start + deg)
__device__ int     g_cursor[NODES];
__device__ int     g_csr[EDGES];          // src indices grouped by dst
__device__ int     g_bsum[512];
__device__ float   g_hg  [GRAPHS * DH];

// ---------------------------------------------------------------------------
// Degree / normalization
// ---------------------------------------------------------------------------
__global__ void k_zero_deg() {
    int i = blockIdx.x * blockDim.x + threadIdx.x;
    if (i < NODES) g_deg[i] = 0;
}

__global__ void k_count_deg(const int* __restrict__ ei) {
    int e = blockIdx.x * blockDim.x + threadIdx.x;
    if (e < EDGES) atomicAdd(&g_deg[ei[EDGES + e]], 1);
}

__global__ void k_dinv() {
    int i = blockIdx.x * blockDim.x + threadIdx.x;
    if (i < NODES) g_dinv[i] = rsqrtf((float)(g_deg[i] + 1));  // +1 self loop
}

// ---------------------------------------------------------------------------
// CSR build: 3-kernel exclusive scan of g_deg, then atomic-cursor fill.
// ---------------------------------------------------------------------------
__global__ void k_scan_blocksum() {          // grid NB, block 256
    int i = blockIdx.x * 256 + threadIdx.x;
    int v = (i < NODES) ? g_deg[i] : 0;
    __shared__ int wsum[8];
#pragma unroll
    for (int off = 16; off > 0; off >>= 1) v += __shfl_xor_sync(~0u, v, off);
    if ((threadIdx.x & 31) == 0) wsum[threadIdx.x >> 5] = v;
    __syncthreads();
    if (threadIdx.x < 8) {
        int s = wsum[threadIdx.x];
#pragma unroll
        for (int off = 4; off > 0; off >>= 1) s += __shfl_xor_sync(0xFFu, s, off);
        if (threadIdx.x == 0) g_bsum[blockIdx.x] = s;
    }
}

__global__ void k_scan_top() {               // single block of 512
    __shared__ int sh[512];
    int t = threadIdx.x;
    int v = (t < NB) ? g_bsum[t] : 0;
    sh[t] = v;
    __syncthreads();
    for (int off = 1; off < 512; off <<= 1) {
        int add = (t >= off) ? sh[t - off] : 0;
        __syncthreads();
        sh[t] += add;
        __syncthreads();
    }
    if (t < NB) g_bsum[t] = sh[t] - v;       // exclusive
}

__global__ void k_scan_apply() {             // grid NB, block 256
    __shared__ int sh[256];
    int i = blockIdx.x * 256 + threadIdx.x;
    int t = threadIdx.x;
    int v = (i < NODES) ? g_deg[i] : 0;
    sh[t] = v;
    __syncthreads();
    for (int off = 1; off < 256; off <<= 1) {
        int add = (t >= off) ? sh[t - off] : 0;
        __syncthreads();
        sh[t] += add;
        __syncthreads();
    }
    if (i < NODES) {
        int start = g_bsum[blockIdx.x] + sh[t] - v;
        g_rowptr[i] = start;
        g_cursor[i] = start;
    }
}

__global__ void k_csr_fill(const int* __restrict__ ei) {
    int e = blockIdx.x * blockDim.x + threadIdx.x;
    if (e < EDGES) {
        int src = ei[e], dst = ei[EDGES + e];
        int pos = atomicAdd(&g_cursor[dst], 1);
        g_csr[pos] = src;
    }
}

// ---------------------------------------------------------------------------
// Tensor-core GEMM: m_row = (pre(in_row)) @ W * dinv[row] -> fp16 g_mh.
// pre(in) = in                      (use_pre == 0, first layer reads x)
// pre(in) = relu(in*dinv[row] + b)  (use_pre == 1, reads g_agg of prev layer)
// Block tile 64x128, K=128 resident in smem. 8 warps, 2(m) x 4(n).
// smem: A 64x128 half (16KB) + B 128x128 half (32KB) = 48KB, XOR-swizzled
// 16B chunks for conflict-free ldmatrix.
// ---------------------------------------------------------------------------
__device__ __forceinline__ uint32_t s2u(const void* p) {
    return (uint32_t)__cvta_generic_to_shared(p);
}

__global__ void __launch_bounds__(256) k_gemm_tc(const float* __restrict__ xin,
                                                 int use_pre,
                                                 const float* __restrict__ W,
                                                 const float* __restrict__ bias) {
    __shared__ __align__(16) __half sA[64 * 128];
    __shared__ __align__(16) __half sB[128 * 128];
    const int tid = threadIdx.x;
    const int r0 = blockIdx.x * 64;
    const float* in = use_pre ? (const float*)g_agg : xin;

    // ---- Load W [128][128] fp32 -> sB half (swizzled). 2048 chunks of 16B.
    const float4* W4 = (const float4*)W;
#pragma unroll
    for (int i = 0; i < 8; i++) {
        int chunk = i * 256 + tid;          // 0..2047
        int row = chunk >> 4, cn = chunk & 15;
        float4 v0 = W4[row * 32 + cn * 2];
        float4 v1 = W4[row * 32 + cn * 2 + 1];
        union { uint4 u; __half2 h[4]; } pk;
        pk.h[0] = __floats2half2_rn(v0.x, v0.y);
        pk.h[1] = __floats2half2_rn(v0.z, v0.w);
        pk.h[2] = __floats2half2_rn(v1.x, v1.y);
        pk.h[3] = __floats2half2_rn(v1.z, v1.w);
        *(uint4*)(sB + row * 128 + ((cn ^ (row & 7)) << 3)) = pk.u;
    }

    // ---- Load A tile [64][128] with fused pre-transform. 1024 chunks.
#pragma unroll
    for (int i = 0; i < 4; i++) {
        int chunk = i * 256 + tid;          // 0..1023
        int row = chunk >> 4, cn = chunk & 15;
        int grow = r0 + row;
        float4 v0 = make_float4(0.f, 0.f, 0.f, 0.f);
        float4 v1 = v0;
        if (grow < NODES) {
            v0 = ((const float4*)in)[grow * 32 + cn * 2];
            v1 = ((const float4*)in)[grow * 32 + cn * 2 + 1];
            if (use_pre) {
                float di = g_dinv[grow];
                const float* bp = bias + cn * 8;
                v0.x = fmaxf(fmaf(v0.x, di, bp[0]), 0.f);
                v0.y = fmaxf(fmaf(v0.y, di, bp[1]), 0.f);
                v0.z = fmaxf(fmaf(v0.z, di, bp[2]), 0.f);
                v0.w = fmaxf(fmaf(v0.w, di, bp[3]), 0.f);
                v1.x = fmaxf(fmaf(v1.x, di, bp[4]), 0.f);
                v1.y = fmaxf(fmaf(v1.y, di, bp[5]), 0.f);
                v1.z = fmaxf(fmaf(v1.z, di, bp[6]), 0.f);
                v1.w = fmaxf(fmaf(v1.w, di, bp[7]), 0.f);
            }
        }
        union { uint4 u; __half2 h[4]; } pk;
        pk.h[0] = __floats2half2_rn(v0.x, v0.y);
        pk.h[1] = __floats2half2_rn(v0.z, v0.w);
        pk.h[2] = __floats2half2_rn(v1.x, v1.y);
        pk.h[3] = __floats2half2_rn(v1.z, v1.w);
        *(uint4*)(sA + row * 128 + ((cn ^ (row & 7)) << 3)) = pk.u;
    }
    __syncthreads();

    const int lane = tid & 31, wid = tid >> 5;
    const int wm = wid & 1;        // 2 warps over m (32 rows each)
    const int wn = wid >> 1;       // 4 warps over n (32 cols each)
    const uint32_t sAu = s2u(sA), sBu = s2u(sB);

    float c[2][4][4];
#pragma unroll
    for (int mt = 0; mt < 2; mt++)
#pragma unroll
        for (int nt = 0; nt < 4; nt++)
#pragma unroll
            for (int q = 0; q < 4; q++) c[mt][nt][q] = 0.f;

#pragma unroll
    for (int ks = 0; ks < 8; ks++) {
        uint32_t a[2][4];
#pragma unroll
        for (int mt = 0; mt < 2; mt++) {
            int r = wm * 32 + mt * 16 + (lane & 15);
            int ch = ks * 2 + (lane >> 4);
            uint32_t addr = sAu + (r << 8) + (((ch) ^ (r & 7)) << 4);
            asm volatile("ldmatrix.sync.aligned.m8n8.x4.shared.b16 {%0,%1,%2,%3}, [%4];"
                         : "=r"(a[mt][0]), "=r"(a[mt][1]), "=r"(a[mt][2]), "=r"(a[mt][3])
                         : "r"(addr));
        }
        uint32_t b[4][2];
#pragma unroll
        for (int nt = 0; nt < 4; nt++) {
            int r = ks * 16 + (lane & 15);
            int ch = wn * 4 + nt;
            uint32_t addr = sBu + (r << 8) + ((ch ^ (r & 7)) << 4);
            asm volatile("ldmatrix.sync.aligned.m8n8.x2.trans.shared.b16 {%0,%1}, [%2];"
                         : "=r"(b[nt][0]), "=r"(b[nt][1])
                         : "r"(addr));
        }
#pragma unroll
        for (int mt = 0; mt < 2; mt++)
#pragma unroll
            for (int nt = 0; nt < 4; nt++) {
                asm volatile(
                    "mma.sync.aligned.m16n8k16.row.col.f32.f16.f16.f32 "
                    "{%0,%1,%2,%3}, {%4,%5,%6,%7}, {%8,%9}, {%0,%1,%2,%3};"
                    : "+f"(c[mt][nt][0]), "+f"(c[mt][nt][1]),
                      "+f"(c[mt][nt][2]), "+f"(c[mt][nt][3])
                    : "r"(a[mt][0]), "r"(a[mt][1]), "r"(a[mt][2]), "r"(a[mt][3]),
                      "r"(b[nt][0]), "r"(b[nt][1]));
            }
    }

    // ---- Epilogue: * dinv[row], pack fp16, store.
#pragma unroll
    for (int mt = 0; mt < 2; mt++) {
        int Rb = r0 + wm * 32 + mt * 16 + (lane >> 2);
#pragma unroll
        for (int hf = 0; hf < 2; hf++) {
            int R = Rb + hf * 8;
            if (R < NODES) {
                float di = g_dinv[R];
#pragma unroll
                for (int nt = 0; nt < 4; nt++) {
                    int C = wn * 32 + nt * 8 + (lane & 3) * 2;
                    __half2 h = __floats2half2_rn(c[mt][nt][hf * 2 + 0] * di,
                                                  c[mt][nt][hf * 2 + 1] * di);
                    *(__half2*)(g_mh + R * 128 + C) = h;
                }
            }
        }
    }
}

// ---------------------------------------------------------------------------
// CSR aggregation: agg[n] = m[n] (self loop) + sum_{src in csr row n} m[src].
// One warp per node; lane owns 4 features (8B half gather per src).
// ---------------------------------------------------------------------------
__global__ void __launch_bounds__(256) k_aggregate() {
    int node = blockIdx.x * 8 + (threadIdx.x >> 5);
    if (node >= NODES) return;
    int lane = threadIdx.x & 31;

    const __half* mh = g_mh;
    const int* __restrict__ csr = g_csr;

    float a0, a1, a2, a3;
    {   // self loop
        union { uint2 u; __half2 h[2]; } pk;
        pk.u = *(const uint2*)(mh + node * 128 + lane * 4);
        float2 f0 = __half22float2(pk.h[0]);
        float2 f1 = __half22float2(pk.h[1]);
        a0 = f0.x; a1 = f0.y; a2 = f1.x; a3 = f1.y;
    }

    int i = g_rowptr[node];
    int e = i + g_deg[node];

    for (; i + 4 <= e; i += 4) {
        int s0 = __ldg(csr + i + 0);
        int s1 = __ldg(csr + i + 1);
        int s2 = __ldg(csr + i + 2);
        int s3 = __ldg(csr + i + 3);
        union { uint2 u; __half2 h[2]; } p0, p1, p2, p3;
        p0.u = *(const uint2*)(mh + s0 * 128 + lane * 4);
        p1.u = *(const uint2*)(mh + s1 * 128 + lane * 4);
        p2.u = *(const uint2*)(mh + s2 * 128 + lane * 4);
        p3.u = *(const uint2*)(mh + s3 * 128 + lane * 4);
        float2 f;
        f = __half22float2(p0.h[0]); a0 += f.x; a1 += f.y;
        f = __half22float2(p0.h[1]); a2 += f.x; a3 += f.y;
        f = __half22float2(p1.h[0]); a0 += f.x; a1 += f.y;
        f = __half22float2(p1.h[1]); a2 += f.x; a3 += f.y;
        f = __half22float2(p2.h[0]); a0 += f.x; a1 += f.y;
        f = __half22float2(p2.h[1]); a2 += f.x; a3 += f.y;
        f = __half22float2(p3.h[0]); a0 += f.x; a1 += f.y;
        f = __half22float2(p3.h[1]); a2 += f.x; a3 += f.y;
    }
    for (; i < e; i++) {
        int s0 = __ldg(csr + i);
        union { uint2 u; __half2 h[2]; } p0;
        p0.u = *(const uint2*)(mh + s0 * 128 + lane * 4);
        float2 f;
        f = __half22float2(p0.h[0]); a0 += f.x; a1 += f.y;
        f = __half22float2(p0.h[1]); a2 += f.x; a3 += f.y;
    }

    g_agg[node * 32 + lane] = make_float4(a0, a1, a2, a3);
}

// ---------------------------------------------------------------------------
// Global mean pool (batch is sorted): block per graph, binary-search range.
// ---------------------------------------------------------------------------
__global__ void __launch_bounds__(128) k_pool(const int* __restrict__ batch,
                                              const float* __restrict__ b3) {
    int g = blockIdx.x, t = threadIdx.x;
    int lo = 0, hi = NODES;
    while (lo < hi) { int m = (lo + hi) >> 1; if (batch[m] < g) lo = m + 1; else hi = m; }
    int s = lo;
    hi = NODES;
    while (lo < hi) { int m = (lo + hi) >> 1; if (batch[m] <= g) lo = m + 1; else hi = m; }
    int e = lo;

    const float* agg = (const float*)g_agg;
    float sum = 0.f;
    for (int n = s; n < e; n++) sum = fmaf(agg[n * 128 + t], g_dinv[n], sum);
    int cnt = e - s;
    g_hg[g * DH + t] = (cnt > 0) ? (sum / (float)cnt + b3[t]) : 0.f;
}

// ---------------------------------------------------------------------------
// Head: softmax(hg @ Wl + bl) — one warp per graph.
// ---------------------------------------------------------------------------
__global__ void __launch_bounds__(32) k_head(const float* __restrict__ Wl,
                                             const float* __restrict__ bl,
                                             float* __restrict__ out) {
    int g = blockIdx.x, lane = threadIdx.x;
    float acc[DOUT];
#pragma unroll
    for (int c = 0; c < DOUT; c++) acc[c] = 0.f;

    for (int k = lane; k < DH; k += 32) {
        float h = g_hg[g * DH + k];
#pragma unroll
        for (int c = 0; c < DOUT; c++) acc[c] = fmaf(h, Wl[k * DOUT + c], acc[c]);
    }
#pragma unroll
    for (int off = 16; off > 0; off >>= 1)
#pragma unroll
        for (int c = 0; c < DOUT; c++)
            acc[c] += __shfl_xor_sync(0xFFFFFFFFu, acc[c], off);

    float mx = -1e30f;
#pragma unroll
    for (int c = 0; c < DOUT; c++) { acc[c] += bl[c]; mx = fmaxf(mx, acc[c]); }
    float sum = 0.f;
#pragma unroll
    for (int c = 0; c < DOUT; c++) { acc[c] = expf(acc[c] - mx); sum += acc[c]; }
    if (lane < DOUT) out[g * DOUT + lane] = acc[lane] / sum;
}

// ---------------------------------------------------------------------------
extern "C" void kernel_launch(void* const* d_in, const int* in_sizes, int n_in,
                              void* d_out, int out_size) {
    const float* x     = (const float*)d_in[0];
    const int*   ei    = (const int*)  d_in[1];
    const int*   batch = (const int*)  d_in[2];
    const float* W1 = (const float*)d_in[3];
    const float* b1 = (const float*)d_in[4];
    const float* W2 = (const float*)d_in[5];
    const float* b2 = (const float*)d_in[6];
    const float* W3 = (const float*)d_in[7];
    const float* b3 = (const float*)d_in[8];
    const float* Wl = (const float*)d_in[9];
    const float* bl = (const float*)d_in[10];
    float* out = (float*)d_out;

    const int gemm_grid = (NODES + 63) / 64;
    const int agg_grid  = (NODES + 7) / 8;

    // degrees + norm
    k_zero_deg <<<(NODES + 255) / 256, 256>>>();
    k_count_deg<<<(EDGES + 255) / 256, 256>>>(ei);
    k_dinv     <<<(NODES + 255) / 256, 256>>>();

    // CSR build (by dst)
    k_scan_blocksum<<<NB, 256>>>();
    k_scan_top     <<<1, 512>>>();
    k_scan_apply   <<<NB, 256>>>();
    k_csr_fill     <<<(EDGES + 255) / 256, 256>>>(ei);

    // Layer 1
    k_gemm_tc  <<<gemm_grid, 256>>>(x, 0, W1, nullptr);
    k_aggregate<<<agg_grid, 256>>>();
    // Layer 2
    k_gemm_tc  <<<gemm_grid, 256>>>(nullptr, 1, W2, b1);
    k_aggregate<<<agg_grid, 256>>>();
    // Layer 3
    k_gemm_tc  <<<gemm_grid, 256>>>(nullptr, 1, W3, b2);
    k_aggregate<<<agg_grid, 256>>>();

    k_pool<<<GRAPHS, 128>>>(batch, b3);
    k_head<<<GRAPHS, 32>>>(Wl, bl, out);
}

// round 5
// speedup vs baseline: 3.1525x; 1.2310x over previous
#include <cuda_runtime.h>
#include <cuda_fp16.h>
#include <cstdint>
#include <stdint.h>
#include <math.h>

// Problem constants (fixed by the reference)
constexpr int NODES  = 100000;
constexpr int EDGES  = 1600000;
constexpr int GRAPHS = 64;
constexpr int DH     = 128;   // DI == DH == 128
constexpr int DOUT   = 10;

constexpr int NB = (NODES + 255) / 256;   // scan blocks (391)

// Scratch (device globals: allocation-free rule)
__device__ __half  g_mh  [NODES * 128];   // messages m[i] = (h@W)*dinv[i], fp16
__device__ __half  g_aggh[NODES * 128];   // aggregate, fp16 (fp32 accum in regs)
__device__ __half  g_wh  [128 * 128];     // current layer weights, fp16, swizzled
__device__ int     g_deg [NODES];
__device__ float   g_dinv[NODES];
__device__ int     g_rowptr[NODES];       // CSR row start (end = start + deg)
__device__ int     g_cursor[NODES];
__device__ int     g_csr[EDGES];          // src indices grouped by dst
__device__ int     g_bsum[512];
__device__ float   g_hg  [GRAPHS * DH];

// ---------------------------------------------------------------------------
// Degree
// ---------------------------------------------------------------------------
__global__ void k_zero_deg() {
    int i = blockIdx.x * blockDim.x + threadIdx.x;
    if (i < NODES) g_deg[i] = 0;
}

__global__ void k_count_deg(const int* __restrict__ ei) {
    int e = blockIdx.x * blockDim.x + threadIdx.x;
    if (e < EDGES) atomicAdd(&g_deg[ei[EDGES + e]], 1);
}

// ---------------------------------------------------------------------------
// CSR build: 3-kernel exclusive scan of g_deg (+dinv fused), atomic-cursor fill.
// ---------------------------------------------------------------------------
__global__ void k_scan_blocksum() {          // grid NB, block 256
    int i = blockIdx.x * 256 + threadIdx.x;
    int v = (i < NODES) ? g_deg[i] : 0;
    __shared__ int wsum[8];
#pragma unroll
    for (int off = 16; off > 0; off >>= 1) v += __shfl_xor_sync(~0u, v, off);
    if ((threadIdx.x & 31) == 0) wsum[threadIdx.x >> 5] = v;
    __syncthreads();
    if (threadIdx.x < 8) {
        int s = wsum[threadIdx.x];
#pragma unroll
        for (int off = 4; off > 0; off >>= 1) s += __shfl_xor_sync(0xFFu, s, off);
        if (threadIdx.x == 0) g_bsum[blockIdx.x] = s;
    }
}

__global__ void k_scan_top() {               // single block of 512
    __shared__ int sh[512];
    int t = threadIdx.x;
    int v = (t < NB) ? g_bsum[t] : 0;
    sh[t] = v;
    __syncthreads();
    for (int off = 1; off < 512; off <<= 1) {
        int add = (t >= off) ? sh[t - off] : 0;
        __syncthreads();
        sh[t] += add;
        __syncthreads();
    }
    if (t < NB) g_bsum[t] = sh[t] - v;       // exclusive
}

__global__ void k_scan_apply() {             // grid NB, block 256
    __shared__ int sh[256];
    int i = blockIdx.x * 256 + threadIdx.x;
    int t = threadIdx.x;
    int v = (i < NODES) ? g_deg[i] : 0;
    sh[t] = v;
    __syncthreads();
    for (int off = 1; off < 256; off <<= 1) {
        int add = (t >= off) ? sh[t - off] : 0;
        __syncthreads();
        sh[t] += add;
        __syncthreads();
    }
    if (i < NODES) {
        int start = g_bsum[blockIdx.x] + sh[t] - v;
        g_rowptr[i] = start;
        g_cursor[i] = start;
        g_dinv[i] = rsqrtf((float)(v + 1));  // +1 self loop (fused here)
    }
}

__global__ void k_csr_fill(const int* __restrict__ ei) {
    int e = blockIdx.x * blockDim.x + threadIdx.x;
    if (e < EDGES) {
        int src = ei[e], dst = ei[EDGES + e];
        int pos = atomicAdd(&g_cursor[dst], 1);
        g_csr[pos] = src;
    }
}

// ---------------------------------------------------------------------------
// Weight pre-convert: fp32 W [128][128] -> fp16, ldmatrix-swizzled layout.
// grid 8, block 256 (2048 chunks of 16B).
// ---------------------------------------------------------------------------
__global__ void k_wconv(const float* __restrict__ W) {
    int chunk = blockIdx.x * 256 + threadIdx.x;  // 0..2047
    int row = chunk >> 4, cn = chunk & 15;
    const float4* W4 = (const float4*)W;
    float4 v0 = W4[row * 32 + cn * 2];
    float4 v1 = W4[row * 32 + cn * 2 + 1];
    union { uint4 u; __half2 h[4]; } pk;
    pk.h[0] = __floats2half2_rn(v0.x, v0.y);
    pk.h[1] = __floats2half2_rn(v0.z, v0.w);
    pk.h[2] = __floats2half2_rn(v1.x, v1.y);
    pk.h[3] = __floats2half2_rn(v1.z, v1.w);
    *(uint4*)(g_wh + row * 128 + ((cn ^ (row & 7)) << 3)) = pk.u;
}

// ---------------------------------------------------------------------------
// Tensor-core GEMM: m_row = (pre(in_row)) @ W * dinv[row] -> fp16 g_mh.
// pre(in) = in                      (use_pre == 0, first layer reads fp32 x)
// pre(in) = relu(in*dinv[row] + b)  (use_pre == 1, reads fp16 g_aggh)
// Block tile 64x128, K=128 resident in smem. 8 warps, 2(m) x 4(n).
// B comes pre-swizzled fp16 from g_wh (raw 16B-chunk copy).
// ---------------------------------------------------------------------------
__device__ __forceinline__ uint32_t s2u(const void* p) {
    return (uint32_t)__cvta_generic_to_shared(p);
}

__global__ void __launch_bounds__(256) k_gemm_tc(const float* __restrict__ xin,
                                                 int use_pre,
                                                 const float* __restrict__ bias) {
    __shared__ __align__(16) __half sA[64 * 128];
    __shared__ __align__(16) __half sB[128 * 128];
    const int tid = threadIdx.x;
    const int r0 = blockIdx.x * 64;

    // ---- B: raw copy of pre-swizzled fp16 weights (2048 x 16B).
    const uint4* wsrc = (const uint4*)g_wh;
    uint4* bdst = (uint4*)sB;
#pragma unroll
    for (int i = 0; i < 8; i++) bdst[i * 256 + tid] = __ldg(wsrc + i * 256 + tid);

    // ---- A tile [64][128] with fused pre-transform. 1024 chunks of 16B.
#pragma unroll
    for (int i = 0; i < 4; i++) {
        int chunk = i * 256 + tid;          // 0..1023
        int row = chunk >> 4, cn = chunk & 15;
        int grow = r0 + row;
        union { uint4 u; __half2 h[4]; } pk;
        if (grow >= NODES) {
            pk.u = make_uint4(0, 0, 0, 0);
        } else if (use_pre) {
            union { uint4 u; __half2 h[4]; } in;
            in.u = *(const uint4*)(g_aggh + grow * 128 + cn * 8);
            float di = g_dinv[grow];
            const float* bp = bias + cn * 8;
            float2 f0 = __half22float2(in.h[0]);
            float2 f1 = __half22float2(in.h[1]);
            float2 f2 = __half22float2(in.h[2]);
            float2 f3 = __half22float2(in.h[3]);
            f0.x = fmaxf(fmaf(f0.x, di, bp[0]), 0.f);
            f0.y = fmaxf(fmaf(f0.y, di, bp[1]), 0.f);
            f1.x = fmaxf(fmaf(f1.x, di, bp[2]), 0.f);
            f1.y = fmaxf(fmaf(f1.y, di, bp[3]), 0.f);
            f2.x = fmaxf(fmaf(f2.x, di, bp[4]), 0.f);
            f2.y = fmaxf(fmaf(f2.y, di, bp[5]), 0.f);
            f3.x = fmaxf(fmaf(f3.x, di, bp[6]), 0.f);
            f3.y = fmaxf(fmaf(f3.y, di, bp[7]), 0.f);
            pk.h[0] = __floats2half2_rn(f0.x, f0.y);
            pk.h[1] = __floats2half2_rn(f1.x, f1.y);
            pk.h[2] = __floats2half2_rn(f2.x, f2.y);
            pk.h[3] = __floats2half2_rn(f3.x, f3.y);
        } else {
            float4 v0 = ((const float4*)xin)[grow * 32 + cn * 2];
            float4 v1 = ((const float4*)xin)[grow * 32 + cn * 2 + 1];
            pk.h[0] = __floats2half2_rn(v0.x, v0.y);
            pk.h[1] = __floats2half2_rn(v0.z, v0.w);
            pk.h[2] = __floats2half2_rn(v1.x, v1.y);
            pk.h[3] = __floats2half2_rn(v1.z, v1.w);
        }
        *(uint4*)(sA + row * 128 + ((cn ^ (row & 7)) << 3)) = pk.u;
    }
    __syncthreads();

    const int lane = tid & 31, wid = tid >> 5;
    const int wm = wid & 1;        // 2 warps over m (32 rows each)
    const int wn = wid >> 1;       // 4 warps over n (32 cols each)
    const uint32_t sAu = s2u(sA), sBu = s2u(sB);

    float c[2][4][4];
#pragma unroll
    for (int mt = 0; mt < 2; mt++)
#pragma unroll
        for (int nt = 0; nt < 4; nt++)
#pragma unroll
            for (int q = 0; q < 4; q++) c[mt][nt][q] = 0.f;

#pragma unroll
    for (int ks = 0; ks < 8; ks++) {
        uint32_t a[2][4];
#pragma unroll
        for (int mt = 0; mt < 2; mt++) {
            int r = wm * 32 + mt * 16 + (lane & 15);
            int ch = ks * 2 + (lane >> 4);
            uint32_t addr = sAu + (r << 8) + ((ch ^ (r & 7)) << 4);
            asm volatile("ldmatrix.sync.aligned.m8n8.x4.shared.b16 {%0,%1,%2,%3}, [%4];"
                         : "=r"(a[mt][0]), "=r"(a[mt][1]), "=r"(a[mt][2]), "=r"(a[mt][3])
                         : "r"(addr));
        }
        uint32_t b[4][2];
#pragma unroll
        for (int nt = 0; nt < 4; nt++) {
            int r = ks * 16 + (lane & 15);
            int ch = wn * 4 + nt;
            uint32_t addr = sBu + (r << 8) + ((ch ^ (r & 7)) << 4);
            asm volatile("ldmatrix.sync.aligned.m8n8.x2.trans.shared.b16 {%0,%1}, [%2];"
                         : "=r"(b[nt][0]), "=r"(b[nt][1])
                         : "r"(addr));
        }
#pragma unroll
        for (int mt = 0; mt < 2; mt++)
#pragma unroll
            for (int nt = 0; nt < 4; nt++) {
                asm volatile(
                    "mma.sync.aligned.m16n8k16.row.col.f32.f16.f16.f32 "
                    "{%0,%1,%2,%3}, {%4,%5,%6,%7}, {%8,%9}, {%0,%1,%2,%3};"
                    : "+f"(c[mt][nt][0]), "+f"(c[mt][nt][1]),
                      "+f"(c[mt][nt][2]), "+f"(c[mt][nt][3])
                    : "r"(a[mt][0]), "r"(a[mt][1]), "r"(a[mt][2]), "r"(a[mt][3]),
                      "r"(b[nt][0]), "r"(b[nt][1]));
            }
    }

    // ---- Epilogue: * dinv[row], pack fp16, store.
#pragma unroll
    for (int mt = 0; mt < 2; mt++) {
        int Rb = r0 + wm * 32 + mt * 16 + (lane >> 2);
#pragma unroll
        for (int hf = 0; hf < 2; hf++) {
            int R = Rb + hf * 8;
            if (R < NODES) {
                float di = g_dinv[R];
#pragma unroll
                for (int nt = 0; nt < 4; nt++) {
                    int C = wn * 32 + nt * 8 + (lane & 3) * 2;
                    __half2 h = __floats2half2_rn(c[mt][nt][hf * 2 + 0] * di,
                                                  c[mt][nt][hf * 2 + 1] * di);
                    *(__half2*)(g_mh + R * 128 + C) = h;
                }
            }
        }
    }
}

// ---------------------------------------------------------------------------
// CSR aggregation: agg[n] = m[n] (self loop) + sum_{src in csr row n} m[src].
// One warp per node; lane owns 4 features. fp32 accumulate, fp16 store.
// ---------------------------------------------------------------------------
__global__ void __launch_bounds__(256) k_aggregate() {
    int node = blockIdx.x * 8 + (threadIdx.x >> 5);
    if (node >= NODES) return;
    int lane = threadIdx.x & 31;

    const __half* mh = g_mh;
    const int* __restrict__ csr = g_csr;

    float a0, a1, a2, a3;
    {   // self loop
        union { uint2 u; __half2 h[2]; } pk;
        pk.u = *(const uint2*)(mh + node * 128 + lane * 4);
        float2 f0 = __half22float2(pk.h[0]);
        float2 f1 = __half22float2(pk.h[1]);
        a0 = f0.x; a1 = f0.y; a2 = f1.x; a3 = f1.y;
    }

    int i = g_rowptr[node];
    int e = i + g_deg[node];

    for (; i + 4 <= e; i += 4) {
        int s0 = __ldg(csr + i + 0);
        int s1 = __ldg(csr + i + 1);
        int s2 = __ldg(csr + i + 2);
        int s3 = __ldg(csr + i + 3);
        union { uint2 u; __half2 h[2]; } p0, p1, p2, p3;
        p0.u = *(const uint2*)(mh + s0 * 128 + lane * 4);
        p1.u = *(const uint2*)(mh + s1 * 128 + lane * 4);
        p2.u = *(const uint2*)(mh + s2 * 128 + lane * 4);
        p3.u = *(const uint2*)(mh + s3 * 128 + lane * 4);
        float2 f;
        f = __half22float2(p0.h[0]); a0 += f.x; a1 += f.y;
        f = __half22float2(p0.h[1]); a2 += f.x; a3 += f.y;
        f = __half22float2(p1.h[0]); a0 += f.x; a1 += f.y;
        f = __half22float2(p1.h[1]); a2 += f.x; a3 += f.y;
        f = __half22float2(p2.h[0]); a0 += f.x; a1 += f.y;
        f = __half22float2(p2.h[1]); a2 += f.x; a3 += f.y;
        f = __half22float2(p3.h[0]); a0 += f.x; a1 += f.y;
        f = __half22float2(p3.h[1]); a2 += f.x; a3 += f.y;
    }
    for (; i < e; i++) {
        int s0 = __ldg(csr + i);
        union { uint2 u; __half2 h[2]; } p0;
        p0.u = *(const uint2*)(mh + s0 * 128 + lane * 4);
        float2 f;
        f = __half22float2(p0.h[0]); a0 += f.x; a1 += f.y;
        f = __half22float2(p0.h[1]); a2 += f.x; a3 += f.y;
    }

    union { uint2 u; __half2 h[2]; } outp;
    outp.h[0] = __floats2half2_rn(a0, a1);
    outp.h[1] = __floats2half2_rn(a2, a3);
    *(uint2*)(g_aggh + node * 128 + lane * 4) = outp.u;
}

// ---------------------------------------------------------------------------
// Global mean pool (batch is sorted): block per graph, binary-search range.
// Final conv output for node n, feat t = agg[n][t]*dinv[n] + b3[t].
// ---------------------------------------------------------------------------
__global__ void __launch_bounds__(128) k_pool(const int* __restrict__ batch,
                                              const float* __restrict__ b3) {
    int g = blockIdx.x, t = threadIdx.x;
    int lo = 0, hi = NODES;
    while (lo < hi) { int m = (lo + hi) >> 1; if (batch[m] < g) lo = m + 1; else hi = m; }
    int s = lo;
    hi = NODES;
    while (lo < hi) { int m = (lo + hi) >> 1; if (batch[m] <= g) lo = m + 1; else hi = m; }
    int e = lo;

    float sum = 0.f;
    for (int n = s; n < e; n++)
        sum = fmaf(__half2float(g_aggh[n * 128 + t]), g_dinv[n], sum);
    int cnt = e - s;
    g_hg[g * DH + t] = (cnt > 0) ? (sum / (float)cnt + b3[t]) : 0.f;
}

// ---------------------------------------------------------------------------
// Head: softmax(hg @ Wl + bl) — one warp per graph.
// ---------------------------------------------------------------------------
__global__ void __launch_bounds__(32) k_head(const float* __restrict__ Wl,
                                             const float* __restrict__ bl,
                                             float* __restrict__ out) {
    int g = blockIdx.x, lane = threadIdx.x;
    float acc[DOUT];
#pragma unroll
    for (int c = 0; c < DOUT; c++) acc[c] = 0.f;

    for (int k = lane; k < DH; k += 32) {
        float h = g_hg[g * DH + k];
#pragma unroll
        for (int c = 0; c < DOUT; c++) acc[c] = fmaf(h, Wl[k * DOUT + c], acc[c]);
    }
#pragma unroll
    for (int off = 16; off > 0; off >>= 1)
#pragma unroll
        for (int c = 0; c < DOUT; c++)
            acc[c] += __shfl_xor_sync(0xFFFFFFFFu, acc[c], off);

    float mx = -1e30f;
#pragma unroll
    for (int c = 0; c < DOUT; c++) { acc[c] += bl[c]; mx = fmaxf(mx, acc[c]); }
    float sum = 0.f;
#pragma unroll
    for (int c = 0; c < DOUT; c++) { acc[c] = expf(acc[c] - mx); sum += acc[c]; }
    if (lane < DOUT) out[g * DOUT + lane] = acc[lane] / sum;
}

// ---------------------------------------------------------------------------
extern "C" void kernel_launch(void* const* d_in, const int* in_sizes, int n_in,
                              void* d_out, int out_size) {
    const float* x     = (const float*)d_in[0];
    const int*   ei    = (const int*)  d_in[1];
    const int*   batch = (const int*)  d_in[2];
    const float* W1 = (const float*)d_in[3];
    const float* b1 = (const float*)d_in[4];
    const float* W2 = (const float*)d_in[5];
    const float* b2 = (const float*)d_in[6];
    const float* W3 = (const float*)d_in[7];
    const float* b3 = (const float*)d_in[8];
    const float* Wl = (const float*)d_in[9];
    const float* bl = (const float*)d_in[10];
    float* out = (float*)d_out;

    const int gemm_grid = (NODES + 63) / 64;
    const int agg_grid  = (NODES + 7) / 8;

    // degrees
    k_zero_deg <<<(NODES + 255) / 256, 256>>>();
    k_count_deg<<<(EDGES + 255) / 256, 256>>>(ei);

    // CSR build (by dst) + dinv
    k_scan_blocksum<<<NB, 256>>>();
    k_scan_top     <<<1, 512>>>();
    k_scan_apply   <<<NB, 256>>>();
    k_csr_fill     <<<(EDGES + 255) / 256, 256>>>(ei);

    // Layer 1
    k_wconv    <<<8, 256>>>(W1);
    k_gemm_tc  <<<gemm_grid, 256>>>(x, 0, nullptr);
    k_aggregate<<<agg_grid, 256>>>();
    // Layer 2
    k_wconv    <<<8, 256>>>(W2);
    k_gemm_tc  <<<gemm_grid, 256>>>(nullptr, 1, b1);
    k_aggregate<<<agg_grid, 256>>>();
    // Layer 3
    k_wconv    <<<8, 256>>>(W3);
    k_gemm_tc  <<<gemm_grid, 256>>>(nullptr, 1, b2);
    k_aggregate<<<agg_grid, 256>>>();

    k_pool<<<GRAPHS, 128>>>(batch, b3);
    k_head<<<GRAPHS, 32>>>(Wl, bl, out);
}

// round 7
// speedup vs baseline: 3.2091x; 1.0180x over previous
#include <cuda_runtime.h>
#include <cuda_fp16.h>
#include <cstdint>
#include <stdint.h>
#include <math.h>

// Problem constants (fixed by the reference)
constexpr int NODES  = 100000;
constexpr int EDGES  = 1600000;
constexpr int GRAPHS = 64;
constexpr int DH     = 128;   // DI == DH == 128
constexpr int DOUT   = 10;

constexpr int NB = (NODES + 255) / 256;   // scan blocks (391)

// Scratch (device globals: allocation-free rule)
__device__ __half  g_mh  [NODES * 128];   // messages m[i] = (h@W)*dinv[i], fp16
__device__ __half  g_aggh[NODES * 128];   // aggregate, fp16 (fp32 accum in regs)
__device__ __half  g_wh  [3 * 128 * 128]; // all 3 layers' weights, fp16, swizzled
__device__ int     g_deg [NODES];
__device__ float   g_dinv[NODES];
__device__ int     g_rowptr[NODES];       // CSR row start (end = start + deg)
__device__ int     g_cursor[NODES];
__device__ int     g_csr[EDGES];          // src indices grouped by dst
__device__ int     g_bsum[512];

// ---------------------------------------------------------------------------
// Degree
// ---------------------------------------------------------------------------
__global__ void k_zero_deg() {
    int i = blockIdx.x * blockDim.x + threadIdx.x;
    if (i < NODES) g_deg[i] = 0;
}

__global__ void k_count_deg(const int* __restrict__ ei) {   // 2 edges/thread
    int e2 = blockIdx.x * blockDim.x + threadIdx.x;
    if (e2 < EDGES / 2) {
        int2 d = ((const int2*)(ei + EDGES))[e2];
        atomicAdd(&g_deg[d.x], 1);
        atomicAdd(&g_deg[d.y], 1);
    }
}

// ---------------------------------------------------------------------------
// CSR build: 3-kernel exclusive scan of g_deg (+dinv fused), atomic-cursor fill.
// ---------------------------------------------------------------------------
__global__ void k_scan_blocksum() {          // grid NB, block 256
    int i = blockIdx.x * 256 + threadIdx.x;
    int v = (i < NODES) ? g_deg[i] : 0;
    __shared__ int wsum[8];
#pragma unroll
    for (int off = 16; off > 0; off >>= 1) v += __shfl_xor_sync(~0u, v, off);
    if ((threadIdx.x & 31) == 0) wsum[threadIdx.x >> 5] = v;
    __syncthreads();
    if (threadIdx.x < 8) {
        int s = wsum[threadIdx.x];
#pragma unroll
        for (int off = 4; off > 0; off >>= 1) s += __shfl_xor_sync(0xFFu, s, off);
        if (threadIdx.x == 0) g_bsum[blockIdx.x] = s;
    }
}

__global__ void k_scan_top() {               // single block of 512
    __shared__ int sh[512];
    int t = threadIdx.x;
    int v = (t < NB) ? g_bsum[t] : 0;
    sh[t] = v;
    __syncthreads();
    for (int off = 1; off < 512; off <<= 1) {
        int add = (t >= off) ? sh[t - off] : 0;
        __syncthreads();
        sh[t] += add;
        __syncthreads();
    }
    if (t < NB) g_bsum[t] = sh[t] - v;       // exclusive
}

__global__ void k_scan_apply() {             // grid NB, block 256
    __shared__ int sh[256];
    int i = blockIdx.x * 256 + threadIdx.x;
    int t = threadIdx.x;
    int v = (i < NODES) ? g_deg[i] : 0;
    sh[t] = v;
    __syncthreads();
    for (int off = 1; off < 256; off <<= 1) {
        int add = (t >= off) ? sh[t - off] : 0;
        __syncthreads();
        sh[t] += add;
        __syncthreads();
    }
    if (i < NODES) {
        int start = g_bsum[blockIdx.x] + sh[t] - v;
        g_rowptr[i] = start;
        g_cursor[i] = start;
        g_dinv[i] = rsqrtf((float)(v + 1));  // +1 self loop (fused here)
    }
}

__global__ void k_csr_fill(const int* __restrict__ ei) {    // 2 edges/thread
    int e2 = blockIdx.x * blockDim.x + threadIdx.x;
    if (e2 < EDGES / 2) {
        int2 s = ((const int2*)ei)[e2];
        int2 d = ((const int2*)(ei + EDGES))[e2];
        int p0 = atomicAdd(&g_cursor[d.x], 1);
        g_csr[p0] = s.x;
        int p1 = atomicAdd(&g_cursor[d.y], 1);
        g_csr[p1] = s.y;
    }
}

// ---------------------------------------------------------------------------
// Weight pre-convert (all 3 layers): fp32 -> fp16, ldmatrix-swizzled.
// grid 24, block 256 (3 x 2048 chunks of 16B).
// ---------------------------------------------------------------------------
__global__ void k_wconv_all(const float* __restrict__ W1,
                            const float* __restrict__ W2,
                            const float* __restrict__ W3) {
    int gchunk = blockIdx.x * 256 + threadIdx.x;   // 0..6143
    int layer = gchunk >> 11;                       // 0..2
    int chunk = gchunk & 2047;
    int row = chunk >> 4, cn = chunk & 15;
    const float* W = (layer == 0) ? W1 : (layer == 1) ? W2 : W3;
    const float4* W4 = (const float4*)W;
    float4 v0 = W4[row * 32 + cn * 2];
    float4 v1 = W4[row * 32 + cn * 2 + 1];
    union { uint4 u; __half2 h[4]; } pk;
    pk.h[0] = __floats2half2_rn(v0.x, v0.y);
    pk.h[1] = __floats2half2_rn(v0.z, v0.w);
    pk.h[2] = __floats2half2_rn(v1.x, v1.y);
    pk.h[3] = __floats2half2_rn(v1.z, v1.w);
    *(uint4*)(g_wh + layer * 128 * 128 + row * 128 + ((cn ^ (row & 7)) << 3)) = pk.u;
}

// ---------------------------------------------------------------------------
// Tensor-core GEMM: m_row = (pre(in_row)) @ W * dinv[row] -> fp16 g_mh.
// pre(in) = in                      (use_pre == 0, first layer reads fp32 x)
// pre(in) = relu(in*dinv[row] + b)  (use_pre == 1, reads fp16 g_aggh)
// Each block: loads sB once, processes TWO 64-row A tiles (W-reuse x2).
// 8 warps, 2(m) x 4(n). XOR-swizzled smem, ldmatrix + mma.m16n8k16.
// ---------------------------------------------------------------------------
__device__ __forceinline__ uint32_t s2u(const void* p) {
    return (uint32_t)__cvta_generic_to_shared(p);
}

__global__ void __launch_bounds__(256) k_gemm_tc(const float* __restrict__ xin,
                                                 int use_pre, int wlayer,
                                                 const float* __restrict__ bias) {
    __shared__ __align__(16) __half sA[64 * 128];
    __shared__ __align__(16) __half sB[128 * 128];
    const int tid = threadIdx.x;

    // ---- B: raw copy of pre-swizzled fp16 weights (2048 x 16B).
    const uint4* wsrc = (const uint4*)(g_wh + wlayer * 128 * 128);
    uint4* bdst = (uint4*)sB;
#pragma unroll
    for (int i = 0; i < 8; i++) bdst[i * 256 + tid] = __ldg(wsrc + i * 256 + tid);

    const int lane = tid & 31, wid = tid >> 5;
    const int wm = wid & 1;        // 2 warps over m (32 rows each)
    const int wn = wid >> 1;       // 4 warps over n (32 cols each)
    const uint32_t sAu = s2u(sA), sBu = s2u(sB);

    for (int half = 0; half < 2; half++) {
        const int r0 = blockIdx.x * 128 + half * 64;
        if (half) __syncthreads();     // all reads of previous sA done

        // ---- A tile [64][128] with fused pre-transform. 1024 chunks of 16B.
#pragma unroll
        for (int i = 0; i < 4; i++) {
            int chunk = i * 256 + tid;
            int row = chunk >> 4, cn = chunk & 15;
            int grow = r0 + row;
            union { uint4 u; __half2 h[4]; } pk;
            if (grow >= NODES) {
                pk.u = make_uint4(0, 0, 0, 0);
            } else if (use_pre) {
                union { uint4 u; __half2 h[4]; } in;
                in.u = *(const uint4*)(g_aggh + grow * 128 + cn * 8);
                float di = g_dinv[grow];
                const float* bp = bias + cn * 8;
                float2 f0 = __half22float2(in.h[0]);
                float2 f1 = __half22float2(in.h[1]);
                float2 f2 = __half22float2(in.h[2]);
                float2 f3 = __half22float2(in.h[3]);
                f0.x = fmaxf(fmaf(f0.x, di, bp[0]), 0.f);
                f0.y = fmaxf(fmaf(f0.y, di, bp[1]), 0.f);
                f1.x = fmaxf(fmaf(f1.x, di, bp[2]), 0.f);
                f1.y = fmaxf(fmaf(f1.y, di, bp[3]), 0.f);
                f2.x = fmaxf(fmaf(f2.x, di, bp[4]), 0.f);
                f2.y = fmaxf(fmaf(f2.y, di, bp[5]), 0.f);
                f3.x = fmaxf(fmaf(f3.x, di, bp[6]), 0.f);
                f3.y = fmaxf(fmaf(f3.y, di, bp[7]), 0.f);
                pk.h[0] = __floats2half2_rn(f0.x, f0.y);
                pk.h[1] = __floats2half2_rn(f1.x, f1.y);
                pk.h[2] = __floats2half2_rn(f2.x, f2.y);
                pk.h[3] = __floats2half2_rn(f3.x, f3.y);
            } else {
                float4 v0 = ((const float4*)xin)[grow * 32 + cn * 2];
                float4 v1 = ((const float4*)xin)[grow * 32 + cn * 2 + 1];
                pk.h[0] = __floats2half2_rn(v0.x, v0.y);
                pk.h[1] = __floats2half2_rn(v0.z, v0.w);
                pk.h[2] = __floats2half2_rn(v1.x, v1.y);
                pk.h[3] = __floats2half2_rn(v1.z, v1.w);
            }
            *(uint4*)(sA + row * 128 + ((cn ^ (row & 7)) << 3)) = pk.u;
        }
        __syncthreads();

        float c[2][4][4];
#pragma unroll
        for (int mt = 0; mt < 2; mt++)
#pragma unroll
            for (int nt = 0; nt < 4; nt++)
#pragma unroll
                for (int q = 0; q < 4; q++) c[mt][nt][q] = 0.f;

#pragma unroll
        for (int ks = 0; ks < 8; ks++) {
            uint32_t a[2][4];
#pragma unroll
            for (int mt = 0; mt < 2; mt++) {
                int r = wm * 32 + mt * 16 + (lane & 15);
                int ch = ks * 2 + (lane >> 4);
                uint32_t addr = sAu + (r << 8) + ((ch ^ (r & 7)) << 4);
                asm volatile("ldmatrix.sync.aligned.m8n8.x4.shared.b16 {%0,%1,%2,%3}, [%4];"
                             : "=r"(a[mt][0]), "=r"(a[mt][1]), "=r"(a[mt][2]), "=r"(a[mt][3])
                             : "r"(addr));
            }
            uint32_t b[4][2];
#pragma unroll
            for (int nt = 0; nt < 4; nt++) {
                int r = ks * 16 + (lane & 15);
                int ch = wn * 4 + nt;
                uint32_t addr = sBu + (r << 8) + ((ch ^ (r & 7)) << 4);
                asm volatile("ldmatrix.sync.aligned.m8n8.x2.trans.shared.b16 {%0,%1}, [%2];"
                             : "=r"(b[nt][0]), "=r"(b[nt][1])
                             : "r"(addr));
            }
#pragma unroll
            for (int mt = 0; mt < 2; mt++)
#pragma unroll
                for (int nt = 0; nt < 4; nt++) {
                    asm volatile(
                        "mma.sync.aligned.m16n8k16.row.col.f32.f16.f16.f32 "
                        "{%0,%1,%2,%3}, {%4,%5,%6,%7}, {%8,%9}, {%0,%1,%2,%3};"
                        : "+f"(c[mt][nt][0]), "+f"(c[mt][nt][1]),
                          "+f"(c[mt][nt][2]), "+f"(c[mt][nt][3])
                        : "r"(a[mt][0]), "r"(a[mt][1]), "r"(a[mt][2]), "r"(a[mt][3]),
                          "r"(b[nt][0]), "r"(b[nt][1]));
                }
        }

        // ---- Epilogue: * dinv[row], pack fp16, store.
#pragma unroll
        for (int mt = 0; mt < 2; mt++) {
            int Rb = r0 + wm * 32 + mt * 16 + (lane >> 2);
#pragma unroll
            for (int hf = 0; hf < 2; hf++) {
                int R = Rb + hf * 8;
                if (R < NODES) {
                    float di = g_dinv[R];
#pragma unroll
                    for (int nt = 0; nt < 4; nt++) {
                        int C = wn * 32 + nt * 8 + (lane & 3) * 2;
                        __half2 h = __floats2half2_rn(c[mt][nt][hf * 2 + 0] * di,
                                                      c[mt][nt][hf * 2 + 1] * di);
                        *(__half2*)(g_mh + R * 128 + C) = h;
                    }
                }
            }
        }
    }
}

// ---------------------------------------------------------------------------
// CSR aggregation: agg[n] = m[n] (self loop) + sum_{src in csr row n} m[src].
// One warp per node; lane owns 4 features. Unroll 8 -> 8 gathers in flight.
// fp32 accumulate, fp16 store.
// ---------------------------------------------------------------------------
__global__ void __launch_bounds__(256) k_aggregate() {
    int node = blockIdx.x * 8 + (threadIdx.x >> 5);
    if (node >= NODES) return;
    int lane = threadIdx.x & 31;

    const __half* mh = g_mh;
    const int* __restrict__ csr = g_csr;

    float a0, a1, a2, a3;
    {   // self loop
        union { uint2 u; __half2 h[2]; } pk;
        pk.u = *(const uint2*)(mh + node * 128 + lane * 4);
        float2 f0 = __half22float2(pk.h[0]);
        float2 f1 = __half22float2(pk.h[1]);
        a0 = f0.x; a1 = f0.y; a2 = f1.x; a3 = f1.y;
    }

    int i = g_rowptr[node];
    int e = i + g_deg[node];

    for (; i + 8 <= e; i += 8) {
        int s[8];
#pragma unroll
        for (int j = 0; j < 8; j++) s[j] = __ldg(csr + i + j);
        union { uint2 u; __half2 h[2]; } p[8];
#pragma unroll
        for (int j = 0; j < 8; j++)
            p[j].u = *(const uint2*)(mh + s[j] * 128 + lane * 4);
#pragma unroll
        for (int j = 0; j < 8; j++) {
            float2 f;
            f = __half22float2(p[j].h[0]); a0 += f.x; a1 += f.y;
            f = __half22float2(p[j].h[1]); a2 += f.x; a3 += f.y;
        }
    }
    for (; i + 2 <= e; i += 2) {
        int s0 = __ldg(csr + i), s1 = __ldg(csr + i + 1);
        union { uint2 u; __half2 h[2]; } p0, p1;
        p0.u = *(const uint2*)(mh + s0 * 128 + lane * 4);
        p1.u = *(const uint2*)(mh + s1 * 128 + lane * 4);
        float2 f;
        f = __half22float2(p0.h[0]); a0 += f.x; a1 += f.y;
        f = __half22float2(p0.h[1]); a2 += f.x; a3 += f.y;
        f = __half22float2(p1.h[0]); a0 += f.x; a1 += f.y;
        f = __half22float2(p1.h[1]); a2 += f.x; a3 += f.y;
    }
    if (i < e) {
        int s0 = __ldg(csr + i);
        union { uint2 u; __half2 h[2]; } p0;
        p0.u = *(const uint2*)(mh + s0 * 128 + lane * 4);
        float2 f;
        f = __half22float2(p0.h[0]); a0 += f.x; a1 += f.y;
        f = __half22float2(p0.h[1]); a2 += f.x; a3 += f.y;
    }

    union { uint2 u; __half2 h[2]; } outp;
    outp.h[0] = __floats2half2_rn(a0, a1);
    outp.h[1] = __floats2half2_rn(a2, a3);
    *(uint2*)(g_aggh + node * 128 + lane * 4) = outp.u;
}

// ---------------------------------------------------------------------------
// Fused mean pool + head: block per graph, 128 threads.
// hg[t] = mean over graph nodes of (agg*dinv) + b3[t]; then warp 0 does
// softmax(hg @ Wl + bl).
// ---------------------------------------------------------------------------
__global__ void __launch_bounds__(128) k_pool_head(const int* __restrict__ batch,
                                                   const float* __restrict__ b3,
                                                   const float* __restrict__ Wl,
                                                   const float* __restrict__ bl,
                                                   float* __restrict__ out) {
    __shared__ float hg[DH];
    int g = blockIdx.x, t = threadIdx.x;
    int lo = 0, hi = NODES;
    while (lo < hi) { int m = (lo + hi) >> 1; if (batch[m] < g) lo = m + 1; else hi = m; }
    int s = lo;
    hi = NODES;
    while (lo < hi) { int m = (lo + hi) >> 1; if (batch[m] <= g) lo = m + 1; else hi = m; }
    int e = lo;

    float sum = 0.f;
    for (int n = s; n < e; n++)
        sum = fmaf(__half2float(g_aggh[n * 128 + t]), g_dinv[n], sum);
    int cnt = e - s;
    hg[t] = (cnt > 0) ? (sum / (float)cnt + b3[t]) : 0.f;
    __syncthreads();

    if (t < 32) {
        int lane = t;
        float acc[DOUT];
#pragma unroll
        for (int c = 0; c < DOUT; c++) acc[c] = 0.f;
        for (int k = lane; k < DH; k += 32) {
            float h = hg[k];
#pragma unroll
            for (int c = 0; c < DOUT; c++) acc[c] = fmaf(h, Wl[k * DOUT + c], acc[c]);
        }
#pragma unroll
        for (int off = 16; off > 0; off >>= 1)
#pragma unroll
            for (int c = 0; c < DOUT; c++)
                acc[c] += __shfl_xor_sync(0xFFFFFFFFu, acc[c], off);

        float mx = -1e30f;
#pragma unroll
        for (int c = 0; c < DOUT; c++) { acc[c] += bl[c]; mx = fmaxf(mx, acc[c]); }
        float ssum = 0.f;
#pragma unroll
        for (int c = 0; c < DOUT; c++) { acc[c] = expf(acc[c] - mx); ssum += acc[c]; }
        if (lane < DOUT) out[g * DOUT + lane] = acc[lane] / ssum;
    }
}

// ---------------------------------------------------------------------------
extern "C" void kernel_launch(void* const* d_in, const int* in_sizes, int n_in,
                              void* d_out, int out_size) {
    const float* x     = (const float*)d_in[0];
    const int*   ei    = (const int*)  d_in[1];
    const int*   batch = (const int*)  d_in[2];
    const float* W1 = (const float*)d_in[3];
    const float* b1 = (const float*)d_in[4];
    const float* W2 = (const float*)d_in[5];
    const float* b2 = (const float*)d_in[6];
    const float* W3 = (const float*)d_in[7];
    const float* b3 = (const float*)d_in[8];
    const float* Wl = (const float*)d_in[9];
    const float* bl = (const float*)d_in[10];
    float* out = (float*)d_out;

    const int gemm_grid = (NODES + 127) / 128;
    const int agg_grid  = (NODES + 7) / 8;

    // weights (independent of graph structure work below)
    k_wconv_all<<<24, 256>>>(W1, W2, W3);

    // degrees
    k_zero_deg <<<(NODES + 255) / 256, 256>>>();
    k_count_deg<<<(EDGES / 2 + 255) / 256, 256>>>(ei);

    // CSR build (by dst) + dinv
    k_scan_blocksum<<<NB, 256>>>();
    k_scan_top     <<<1, 512>>>();
    k_scan_apply   <<<NB, 256>>>();
    k_csr_fill     <<<(EDGES / 2 + 255) / 256, 256>>>(ei);

    // Layer 1
    k_gemm_tc  <<<gemm_grid, 256>>>(x, 0, 0, nullptr);
    k_aggregate<<<agg_grid, 256>>>();
    // Layer 2
    k_gemm_tc  <<<gemm_grid, 256>>>(nullptr, 1, 1, b1);
    k_aggregate<<<agg_grid, 256>>>();
    // Layer 3
    k_gemm_tc  <<<gemm_grid, 256>>>(nullptr, 1, 2, b2);
    k_aggregate<<<agg_grid, 256>>>();

    k_pool_head<<<GRAPHS, 128>>>(batch, b3, Wl, bl, out);
}